// round 17
// baseline (speedup 1.0000x reference)
#include <cuda_runtime.h>
#include <cuda_bf16.h>
#include <cuda_fp16.h>
#include <cstdint>
#include <cstddef>
#include <math.h>

#define Bsz 16
#define Hh  512
#define Ll  2048
#define Nn  64
#define Tt  64
#define Cc  32

// ---------------- scratch ----------------
__device__ float2   g_G[Hh * Nn];                 // [h][n] : A^64
__device__ uint32_t g_B1h[(size_t)Hh * 6144];     // GEMM1 B frags fp16
__device__ uint32_t g_B2h[(size_t)Hh * 4096];     // GEMM2 B frags fp16
__device__ __half   g_gh[(size_t)Bsz * Hh * Ll];  // gelu (fp16)
__device__ __half   g_Wh[Hh * Hh];                // Wout fp16 [v][u]

// ---------------- helpers ----------------
__device__ __forceinline__ float2 cmul(float2 a, float2 b) {
    return make_float2(a.x * b.x - a.y * b.y, a.x * b.y + a.y * b.x);
}
__device__ __forceinline__ float2 cexp2(float2 z) {
    float e = expf(z.x);
    float s, c;
    sincosf(z.y, &s, &c);
    return make_float2(e * c, e * s);
}
__device__ __forceinline__ float2 cscale(float2 z, float s) {
    return make_float2(z.x * s, z.y * s);
}
__device__ __forceinline__ uint32_t packh(float a, float b) {
    __half2 t = __floats2half2_rn(a, b);
    return *reinterpret_cast<uint32_t*>(&t);
}
__device__ __forceinline__ uint32_t smem_u32(const void* p) {
    return (uint32_t)__cvta_generic_to_shared(p);
}
__device__ __forceinline__ void cpasync16(uint32_t dst, const void* src) {
    asm volatile("cp.async.ca.shared.global [%0],[%1],16;" :: "r"(dst), "l"(src));
}
__device__ __forceinline__ void cp_commit() {
    asm volatile("cp.async.commit_group;");
}
template<int N>
__device__ __forceinline__ void cp_wait() {
    asm volatile("cp.async.wait_group %0;" :: "n"(N));
}
__device__ __forceinline__ void ldsm_x4(uint32_t& r0, uint32_t& r1, uint32_t& r2, uint32_t& r3, uint32_t a) {
    asm volatile("ldmatrix.sync.aligned.m8n8.x4.shared.b16 {%0,%1,%2,%3},[%4];"
                 : "=r"(r0), "=r"(r1), "=r"(r2), "=r"(r3) : "r"(a));
}
__device__ __forceinline__ void ldsm_x4_t(uint32_t& r0, uint32_t& r1, uint32_t& r2, uint32_t& r3, uint32_t a) {
    asm volatile("ldmatrix.sync.aligned.m8n8.x4.trans.shared.b16 {%0,%1,%2,%3},[%4];"
                 : "=r"(r0), "=r"(r1), "=r"(r2), "=r"(r3) : "r"(a));
}
__device__ __forceinline__ void mma_f16(float* d, const uint32_t* a, const uint32_t* b) {
    asm volatile("mma.sync.aligned.m16n8k16.row.col.f32.f16.f16.f32 "
                 "{%0,%1,%2,%3},{%4,%5,%6,%7},{%8,%9},{%0,%1,%2,%3};"
                 : "+f"(d[0]), "+f"(d[1]), "+f"(d[2]), "+f"(d[3])
                 : "r"(a[0]), "r"(a[1]), "r"(a[2]), "r"(a[3]), "r"(b[0]), "r"(b[1]));
}

// ---------------- kernel 1: precompute + fragment packing + W split ----------------
// grid (Hh, 2): y=0 packs B1 (+G, ks), y=1 packs B2; both convert a Wout slice.
// Wk computed ONCE on 64 threads (MUFU-heavy); q>0 threads do exactly 2 cexp2.
__global__ __launch_bounds__(256)
void dss_precompute(const float* __restrict__ log_dt,
                    const float* __restrict__ Lambda,
                    const float* __restrict__ W,
                    const float* __restrict__ D,
                    const float* __restrict__ Wout) {
    int h = blockIdx.x;
    int y = blockIdx.y;
    int t = threadIdx.x;
    int n = t & 63;
    int q = t >> 6;

    // folded splitW: 1024 blocks x 256 threads covers 512*512
    int wi = (h * 2 + y) * 256 + t;
    g_Wh[wi] = __float2half_rn(Wout[wi]);

    __shared__ float2 sA[Nn][66];
    __shared__ float2 sWk[Nn];
    __shared__ float2 sZ[Nn];
    __shared__ float  sks[Tt];
    __shared__ float  kred[Tt][4];

    if (t < 64) {
        float dt_re = expf(log_dt[h * 2 + 0]);
        float dt_im = expf(log_dt[h * 2 + 1]);
        float2 Lam = make_float2(Lambda[n * 2 + 0], Lambda[n * 2 + 1]);
        float2 z = make_float2(dt_re * Lam.x, dt_im * Lam.y);
        bool pos = (Lam.x > 0.0f);
        float2 zn = pos ? make_float2(-z.x, -z.y) : z;

        float2 ez  = cexp2(zn);
        float2 num = make_float2(ez.x - 1.0f, ez.y);
        float2 ezL = cexp2(cscale(zn, (float)Ll));
        float2 den = make_float2(ezL.x - 1.0f, ezL.y);
        float2 x   = cmul(den, Lam);
        float r2   = x.x * x.x + x.y * x.y + 1e-7f;
        float2 recip = make_float2(x.x / r2, -x.y / r2);
        float2 Wc  = make_float2(W[(h * Nn + n) * 2 + 0], W[(h * Nn + n) * 2 + 1]);
        float2 Wk  = cmul(cmul(Wc, num), recip);
        if (pos) Wk = cmul(Wk, cexp2(cscale(z, -(float)(Ll - 1))));
        sWk[n] = Wk;
        sZ[n]  = z;
    }
    __syncthreads();

    // parallel power table: 4 threads per n; q>0 pays 2 cexp2 total
    {
        float2 z  = sZ[n];
        float2 A  = cexp2(z);
        float2 Ap = (q == 0) ? make_float2(1.0f, 0.0f)
                             : cexp2(cscale(z, (float)(16 * q)));
        int pend = (q == 3) ? 65 : 16 * (q + 1);
        for (int p = 16 * q; p < pend; p++) {
            sA[n][p] = Ap;
            Ap = cmul(Ap, A);
        }
    }
    __syncthreads();
    if (y == 0 && t < Nn) g_G[h * Nn + t] = sA[t][64];

    int r    = t & 1;
    int lane = (t >> 1) & 31;
    int rl   = t & 63;

    if (y == 0) {
        // ks reduction, 4-way split over modes
        {
            int m = n;
            float acc = 0.0f;
            for (int qq = q * 16; qq < q * 16 + 16; qq++)
                acc += cmul(sWk[qq], sA[qq][m]).x;
            kred[m][q] = acc;
        }
        __syncthreads();
        if (t < Tt)
            sks[t] = kred[t][0] + kred[t][1] + kred[t][2] + kred[t][3]
                   + ((t == 0) ? D[h] : 0.0f);   // skip folded into tap 0
        __syncthreads();

        // B1 pack: incremental nt/ks (no div/mod)
        int rest = t >> 6;      // 0..3
        int nt = rest, ks = 0;
        #pragma unroll 4
        for (int k = 0; k < 24; k++) {
            int i   = (rest << 6) | rl;
            int k0  = ks * 16 + (lane & 3) * 2 + r * 8;
            int col = nt * 8 + (lane >> 2);
            float v0, v1;
            if (col < 128) {
                float2 a0 = sA[col >> 1][63 - k0];
                float2 a1 = sA[col >> 1][63 - (k0 + 1)];
                v0 = (col & 1) ? a0.y : a0.x;
                v1 = (col & 1) ? a1.y : a1.x;
            } else {
                int jout = col - 128;
                int d0 = jout - k0;
                int d1 = jout - (k0 + 1);
                v0 = (d0 >= 0) ? sks[d0] : 0.0f;
                v1 = (d1 >= 0) ? sks[d1] : 0.0f;
            }
            g_B1h[(size_t)h * 6144 + i] = packh(v0, v1);
            rest += 4; nt += 4;
            if (nt >= 24) { nt -= 24; ks++; }
        }
    } else {
        int rest = t >> 6;
        #pragma unroll 4
        for (int k = 0; k < 16; k++) {
            int i   = (rest << 6) | rl;
            int nt  = rest & 7;
            int ks  = rest >> 3;
            int k0  = ks * 16 + (lane & 3) * 2 + r * 8;
            int j   = nt * 8 + (lane >> 2);
            float v0, v1;
            {
                int nn = k0 >> 1;
                float2 e = cmul(sWk[nn], sA[nn][j + 1]);
                v0 = (k0 & 1) ? -e.y : e.x;
            }
            {
                int nn = (k0 + 1) >> 1;
                float2 e = cmul(sWk[nn], sA[nn][j + 1]);
                v1 = ((k0 + 1) & 1) ? -e.y : e.x;
            }
            g_B2h[(size_t)h * 4096 + i] = packh(v0, v1);
            rest += 4;
        }
    }
}

// ---------------- kernel 2: conv, M=64 (2 batches per block) ----------------
// smem overlay (70656 B):
//   [0,9216)      u_s[64][72] fp16  (dead after GEMM1)
//   [0,17408)     S_s[64][136] fp16 (born at scan)
//   [17408,51200) Yw[64][132] fp32  (dead after scan)
//   [51200,70656) Yv[64][76]  fp32  (lives to epilogue)
#define CONV_SMEM 70656
__global__ __launch_bounds__(256, 2)
void dss_conv(const float* __restrict__ u) {
    extern __shared__ char sm[];
    __half (*u_s)[72]  = (__half(*)[72])(sm);
    __half (*S_s)[136] = (__half(*)[136])(sm);
    float  (*Yw)[132]  = (float(*)[132])(sm + 17408);
    float  (*Yv)[76]   = (float(*)[76])(sm + 51200);

    int b0 = blockIdx.x * 2;
    int h = blockIdx.y;
    int t = threadIdx.x;
    int lane = t & 31;
    int w = t >> 5;
    int g = lane >> 2;
    int tt = lane & 3;

    // hoisted GEMM2 B-fragment loads
    uint2 b2r[8];
    {
        const uint32_t* B2h = g_B2h + (size_t)h * 4096;
        #pragma unroll
        for (int ks = 0; ks < 8; ks++)
            b2r[ks] = ((const uint2*)(B2h + (ks * 8 + w) * 64))[lane];
    }

    // load u for both batches (4096 fp32) -> single fp16 smem [64][72]
    #pragma unroll
    for (int k = 0; k < 4; k++) {
        int i4 = t + k * 256;            // 0..1023
        int elem = i4 * 4;
        int batch = elem >> 11;
        int off = elem & 2047;
        float4 v = *(const float4*)(u + ((size_t)(b0 + batch) * Hh + h) * Ll + off);
        int row = i4 >> 4;               // 0..63
        int j = (i4 & 15) * 4;
        *(uint32_t*)&u_s[row][j]     = packh(v.x, v.y);
        *(uint32_t*)&u_s[row][j + 2] = packh(v.z, v.w);
    }
    __syncthreads();

    // GEMM1: M=64 x N=192 x K=64; warp w covers cols [24w, 24w+24)
    {
        float acc[4][3][4];
        #pragma unroll
        for (int mi = 0; mi < 4; mi++)
            #pragma unroll
            for (int ni = 0; ni < 3; ni++)
                #pragma unroll
                for (int rr = 0; rr < 4; rr++) acc[mi][ni][rr] = 0.0f;

        const uint32_t* B1h = g_B1h + (size_t)h * 6144;
        int arow = lane & 15;
        int acol8 = (lane >> 4) << 3;

        #pragma unroll
        for (int ks = 0; ks < 4; ks++) {
            uint32_t a[4][4];
            #pragma unroll
            for (int mt = 0; mt < 4; mt++)
                ldsm_x4(a[mt][0], a[mt][1], a[mt][2], a[mt][3],
                        smem_u32(&u_s[mt * 16 + arow][ks * 16 + acol8]));
            #pragma unroll
            for (int nt = 0; nt < 3; nt++) {
                int fidx = (ks * 24 + w * 3 + nt) * 64;
                uint2 bh = ((const uint2*)(B1h + fidx))[lane];
                uint32_t bhr[2] = {bh.x, bh.y};
                #pragma unroll
                for (int mt = 0; mt < 4; mt++)
                    mma_f16(acc[mt][nt], a[mt], bhr);
            }
        }
        __syncthreads();   // all ldsm u reads done before Yw/Yv stores & later S overlay
        #pragma unroll
        for (int mt = 0; mt < 4; mt++)
            #pragma unroll
            for (int nt = 0; nt < 3; nt++) {
                int col = w * 24 + nt * 8 + 2 * tt;
                int row = mt * 16 + g;
                if (col < 128) {
                    Yw[row][col]     = acc[mt][nt][0];
                    Yw[row][col + 1] = acc[mt][nt][1];
                    Yw[row + 8][col]     = acc[mt][nt][2];
                    Yw[row + 8][col + 1] = acc[mt][nt][3];
                } else {
                    int cv = col - 128;
                    Yv[row][cv]     = acc[mt][nt][0];
                    Yv[row][cv + 1] = acc[mt][nt][1];
                    Yv[row + 8][cv]     = acc[mt][nt][2];
                    Yv[row + 8][cv + 1] = acc[mt][nt][3];
                }
            }
    }
    __syncthreads();

    // cross-chunk scan: threads 0..127 (t>>6 = batch, t&63 = mode)
    if (t < 128) {
        int batch = t >> 6;
        int n = t & 63;
        float2 G = g_G[h * Nn + n];
        float Sr = 0.0f, Si = 0.0f;
        int n2 = 2 * n;
        int rbase = batch * 32;
        for (int c = 0; c < Cc; c++) {
            float wr = Yw[rbase + c][n2];
            float wi = Yw[rbase + c][n2 + 1];
            *(uint32_t*)&S_s[rbase + c][n2] = packh(Sr, Si);
            float nr = G.x * Sr - G.y * Si + wr;
            float ni = G.x * Si + G.y * Sr + wi;
            Sr = nr; Si = ni;
        }
    }
    __syncthreads();

    // GEMM2: M=64 x N=64 x K=128; warp w covers j in [8w, 8w+8)
    float acc2[4][4];
    #pragma unroll
    for (int mi = 0; mi < 4; mi++)
        #pragma unroll
        for (int rr = 0; rr < 4; rr++) acc2[mi][rr] = 0.0f;
    {
        int arow = lane & 15;
        int acol8 = (lane >> 4) << 3;
        #pragma unroll
        for (int ks = 0; ks < 8; ks++) {
            uint32_t a[4][4];
            #pragma unroll
            for (int mt = 0; mt < 4; mt++)
                ldsm_x4(a[mt][0], a[mt][1], a[mt][2], a[mt][3],
                        smem_u32(&S_s[mt * 16 + arow][ks * 16 + acol8]));
            uint32_t bhr[2] = {b2r[ks].x, b2r[ks].y};
            #pragma unroll
            for (int mt = 0; mt < 4; mt++)
                mma_f16(acc2[mt], a[mt], bhr);
        }
    }

    // epilogue: + (within+skip) from Yv, gelu -> fp16
    {
        int j0 = w * 8 + 2 * tt;
        #pragma unroll
        for (int mt = 0; mt < 4; mt++) {
            #pragma unroll
            for (int rr = 0; rr < 2; rr++) {
                int rowidx = mt * 16 + g + rr * 8;     // 0..63
                int batch = rowidx >> 5;
                int c = rowidx & 31;
                float y0 = acc2[mt][rr * 2 + 0] + Yv[rowidx][j0];
                float y1 = acc2[mt][rr * 2 + 1] + Yv[rowidx][j0 + 1];
                y0 = 0.5f * y0 * (1.0f + erff(y0 * 0.70710678118654752f));
                y1 = 0.5f * y1 * (1.0f + erff(y1 * 0.70710678118654752f));
                size_t base = ((size_t)(b0 + batch) * Hh + h) * Ll;
                *(uint32_t*)&g_gh[base + c * 64 + j0] = packh(y0, y1);
            }
        }
    }
}

// ---------------- kernel 3: outproj fp16 GEMM, 3-stage cp.async, 1 sync/stage ----------------
// dynamic smem: As[3][128][40] @0 (30720 B), Bs[3][32][136] @30720 (26112 B)
#define OP_SMEM 56832
__global__ __launch_bounds__(256)
void dss_outproj(const float* __restrict__ bias, float* __restrict__ out) {
    extern __shared__ __half smo[];
    __half* Asb = smo;            // stage p at half-offset p*5120, row pitch 40
    __half* Bsb = smo + 15360;    // stage p at half-offset p*4352, row pitch 136

    int b  = blockIdx.z;
    int v0 = blockIdx.y * 128;
    int l0 = blockIdx.x * 128;
    int t  = threadIdx.x;
    int lane = t & 31;
    int wrp  = t >> 5;
    int wv = wrp >> 2;
    int wl = wrp & 3;

    float acc[4][4][4];
    #pragma unroll
    for (int i = 0; i < 4; i++)
        #pragma unroll
        for (int j = 0; j < 4; j++)
            #pragma unroll
            for (int r = 0; r < 4; r++) acc[i][j][r] = 0.0f;

    const int arow = t >> 2;
    const int aseg = (t & 3) * 8;
    const int brow = t >> 4;
    const int bseg = (t & 15) * 8;

    auto prefetch = [&](int s) {
        int kt = s * 32;
        int p = s % 3;
        #pragma unroll
        for (int rep = 0; rep < 2; rep++) {
            int r128 = rep * 64 + arow;
            cpasync16(smem_u32(Asb + p * 5120 + r128 * 40 + aseg),
                      &g_Wh[(size_t)(v0 + r128) * Hh + kt + aseg]);
            int r32 = rep * 16 + brow;
            cpasync16(smem_u32(Bsb + p * 4352 + r32 * 136 + bseg),
                      &g_gh[((size_t)b * Hh + kt + r32) * Ll + l0 + bseg]);
        }
        cp_commit();
    };

    prefetch(0);
    prefetch(1);

    for (int s = 0; s < 16; s++) {
        if (s < 15) cp_wait<1>();
        else        cp_wait<0>();
        __syncthreads();
        if (s + 2 < 16) prefetch(s + 2);

        int p = s % 3;
        const __half* Ap = Asb + p * 5120;
        const __half* Bp = Bsb + p * 4352;
        #pragma unroll
        for (int kk = 0; kk < 2; kk++) {
            uint32_t a[4][4], bb[4][2];
            int ar = (lane & 15);
            int ac = kk * 16 + ((lane >> 4) << 3);
            #pragma unroll
            for (int mi = 0; mi < 4; mi++) {
                int row = wv * 64 + mi * 16 + ar;
                ldsm_x4(a[mi][0], a[mi][1], a[mi][2], a[mi][3],
                        smem_u32(Ap + row * 40 + ac));
            }
            int brw = kk * 16 + (lane & 15);
            #pragma unroll
            for (int nj = 0; nj < 2; nj++) {
                int bc = wl * 32 + nj * 16 + ((lane >> 4) << 3);
                uint32_t r0, r1, r2, r3;
                ldsm_x4_t(r0, r1, r2, r3, smem_u32(Bp + brw * 136 + bc));
                bb[2 * nj][0] = r0; bb[2 * nj][1] = r1;
                bb[2 * nj + 1][0] = r2; bb[2 * nj + 1][1] = r3;
            }
            #pragma unroll
            for (int mi = 0; mi < 4; mi++)
                #pragma unroll
                for (int ni = 0; ni < 4; ni++)
                    mma_f16(acc[mi][ni], a[mi], bb[ni]);
        }
    }

    int row = lane >> 2;
    int col = (lane & 3) * 2;
    #pragma unroll
    for (int mi = 0; mi < 4; mi++) {
        int v = v0 + wv * 64 + mi * 16 + row;
        float bs0 = bias[v];
        float bs1 = bias[v + 8];
        float* o0 = out + ((size_t)b * Hh + v) * Ll;
        float* o1 = out + ((size_t)b * Hh + v + 8) * Ll;
        #pragma unroll
        for (int ni = 0; ni < 4; ni++) {
            int l = l0 + wl * 32 + ni * 8 + col;
            float2 p0 = make_float2(acc[mi][ni][0] + bs0, acc[mi][ni][1] + bs0);
            float2 p1 = make_float2(acc[mi][ni][2] + bs1, acc[mi][ni][3] + bs1);
            *(float2*)&o0[l] = p0;
            *(float2*)&o1[l] = p1;
        }
    }
}

// ---------------- launch ----------------
extern "C" void kernel_launch(void* const* d_in, const int* in_sizes, int n_in,
                              void* d_out, int out_size) {
    const float* u       = (const float*)d_in[0];
    const float* log_dt  = (const float*)d_in[1];
    const float* Lambda  = (const float*)d_in[2];
    const float* W       = (const float*)d_in[3];
    const float* D       = (const float*)d_in[4];
    const float* Wout    = (const float*)d_in[5];
    const float* bias    = (const float*)d_in[6];
    float* out = (float*)d_out;

    static bool attr_set = false;
    if (!attr_set) {
        cudaFuncSetAttribute(dss_conv, cudaFuncAttributeMaxDynamicSharedMemorySize, CONV_SMEM);
        cudaFuncSetAttribute(dss_outproj, cudaFuncAttributeMaxDynamicSharedMemorySize, OP_SMEM);
        attr_set = true;
    }

    dss_precompute<<<dim3(Hh, 2), 256>>>(log_dt, Lambda, W, D, Wout);
    dss_conv<<<dim3(Bsz / 2, Hh), 256, CONV_SMEM>>>(u);
    dss_outproj<<<dim3(Ll / 128, Hh / 128, Bsz), 256, OP_SMEM>>>(bias, out);
}